// round 17
// baseline (speedup 1.0000x reference)
#include <cuda_runtime.h>
#include <cuda_fp16.h>
#include <math.h>
#include <stdint.h>

#define BATCH 16
#define IMG 56
#define PP 28
#define NPOS 784
#define DIM 256
#define HEADS 8
#define DH 64
#define INNER 512

// ---------------- scratch (static device allocations; no cudaMalloc) -------
__device__ float  g_xpool[BATCH * NPOS * DIM];
__device__ float  g_attn2[BATCH * NPOS * 2];
__device__ float  g_q[BATCH * HEADS * NPOS * 2];
__device__ float  g_k[BATCH * HEADS * NPOS * 2];
__device__ __half g_vmid_h[BATCH * NPOS * DIM];
__device__ __half g_v_h[BATCH * NPOS * INNER];
__device__ __half g_ao_h[BATCH * NPOS * INNER];
__device__ __half g_y28_h[BATCH * NPOS * DIM];   // out-proj result (fp16)
__device__ __half g_pww_h[INNER * DIM];
__device__ __half g_oww_h[DIM * INNER];

__constant__ float c_W25[4] = {-0.10546875f, 0.87890625f, 0.26171875f, -0.03515625f};
__constant__ float c_W75[4] = {-0.03515625f, 0.26171875f, 0.87890625f, -0.10546875f};

// ---------------- helpers ---------------------------------------------------
__device__ __forceinline__ uint32_t pack_h2(float lo, float hi) {
    uint32_t r;
    asm("cvt.rn.f16x2.f32 %0, %1, %2;" : "=r"(r) : "f"(hi), "f"(lo));
    return r;
}
__device__ __forceinline__ uint32_t exp2_h2(float lo, float hi) {
    uint32_t s = pack_h2(lo, hi);
    uint32_t r;
    asm("ex2.approx.f16x2 %0, %1;" : "=r"(r) : "r"(s));
    return r;
}
__device__ __forceinline__ void mma_h(float c[4], uint32_t a0, uint32_t a1,
                                      uint32_t a2, uint32_t a3,
                                      uint32_t b0, uint32_t b1) {
    asm volatile(
        "mma.sync.aligned.m16n8k16.row.col.f32.f16.f16.f32 "
        "{%0,%1,%2,%3},{%4,%5,%6,%7},{%8,%9},{%0,%1,%2,%3};"
        : "+f"(c[0]), "+f"(c[1]), "+f"(c[2]), "+f"(c[3])
        : "r"(a0), "r"(a1), "r"(a2), "r"(a3), "r"(b0), "r"(b1));
}
__device__ __forceinline__ uint32_t smem_u32(const void* p) {
    uint32_t a;
    asm("{ .reg .u64 t; cvta.to.shared.u64 t, %1; cvt.u32.u64 %0, t; }" : "=r"(a) : "l"(p));
    return a;
}

// ---------------- 1) avgpool + stats (px-split, 2ch) + weight convert ------
// grid (5, PP, BATCH), 128 threads. quarter<4: pool; quarter==4: fp16 weights.
__global__ void pool_part_kernel(const float* __restrict__ x,
                                 const float* __restrict__ pw,
                                 const float* __restrict__ ow) {
    __shared__ float srow[7][DIM];
    int quarter = blockIdx.x, py = blockIdx.y, b = blockIdx.z;
    int c2 = threadIdx.x, c = 2 * c2;
    if (quarter == 4) {
        int idx0 = (b * PP + py) * 128 + c2;
        for (int i = idx0; i < INNER * DIM; i += PP * BATCH * 128) {
            g_pww_h[i] = __float2half(pw[i]);
            g_oww_h[i] = __float2half(ow[i]);
        }
        return;
    }
    int lane = c2 & 31, w4 = c2 >> 5;
    int px0 = quarter * 7;
    const float* base = x + (size_t)b * IMG * IMG * DIM + c;
    int rm = 2 * py - 1, r0 = 2 * py, rp = 2 * py + 1;
    bool vm = rm >= 0;

    float2 cs[15];
#pragma unroll
    for (int i = 0; i < 15; i++) {
        int ix = 2 * px0 - 1 + i;
        if ((unsigned)ix < IMG) {
            float2 a = *(const float2*)&base[(size_t)(r0 * IMG + ix) * DIM];
            float2 bq = *(const float2*)&base[(size_t)(rp * IMG + ix) * DIM];
            float2 v = make_float2(a.x + bq.x, a.y + bq.y);
            if (vm) {
                float2 m2 = *(const float2*)&base[(size_t)(rm * IMG + ix) * DIM];
                v.x += m2.x; v.y += m2.y;
            }
            cs[i] = v;
        } else cs[i] = make_float2(0.f, 0.f);
    }
    float* outp = g_xpool + ((size_t)b * NPOS + py * PP + px0) * DIM + c;
#pragma unroll
    for (int i = 0; i < 7; i++) {
        float2 pool;
        pool.x = (cs[2 * i].x + cs[2 * i + 1].x + cs[2 * i + 2].x) * (1.f / 9.f);
        pool.y = (cs[2 * i].y + cs[2 * i + 1].y + cs[2 * i + 2].y) * (1.f / 9.f);
        *(float2*)&outp[(size_t)i * DIM] = pool;
        *(float2*)&srow[i][c] = pool;
    }
    __syncthreads();
    for (int px = w4; px < 7; px += 4) {
        float s = 0.f, m = -1e30f;
#pragma unroll
        for (int k = 0; k < 8; k++) {
            float v = srow[px][lane + 32 * k];
            s += v; m = fmaxf(m, v);
        }
#pragma unroll
        for (int o = 16; o > 0; o >>= 1) {
            s += __shfl_down_sync(0xffffffffu, s, o);
            m = fmaxf(m, __shfl_down_sync(0xffffffffu, m, o));
        }
        if (lane == 0) {
            g_attn2[((size_t)b * NPOS + py * PP + px0 + px) * 2 + 0] = s * (1.f / DIM);
            g_attn2[((size_t)b * NPOS + py * PP + px0 + px) * 2 + 1] = m;
        }
    }
}

// ---------------- 3) depthwise+BN+GELU (px-split, 2ch) + qk conv -----------
__global__ void dw_part_kernel(const float* __restrict__ dww, const float* __restrict__ dwb,
                               const float* __restrict__ gamma, const float* __restrict__ beta,
                               const float* __restrict__ mean, const float* __restrict__ var,
                               const float* __restrict__ qw, const float* __restrict__ qb,
                               const float* __restrict__ kw, const float* __restrict__ kb) {
    int quarter = blockIdx.x, py = blockIdx.y, b = blockIdx.z, c2 = threadIdx.x;
    if (quarter == 4) {
        for (int wk = c2; wk < PP * 32; wk += 128) {
            int pl = wk >> 5, tt = wk & 31;
            int p = py * PP + pl;
            int sel = tt >> 4, och = tt & 15;
            const float* w = sel ? kw : qw;
            const float* bi = sel ? kb : qb;
            float* outp = sel ? g_k : g_q;
            int ppy = p / PP, ppx = p % PP;
            float acc = bi[och];
#pragma unroll
            for (int dy = 0; dy < 3; dy++) {
                int iy = ppy - 1 + dy;
                if ((unsigned)iy >= PP) continue;
#pragma unroll
                for (int dx = 0; dx < 3; dx++) {
                    int ix = ppx - 1 + dx;
                    if ((unsigned)ix >= PP) continue;
                    const float* a2 = &g_attn2[((size_t)b * NPOS + iy * PP + ix) * 2];
                    acc += w[((och * 2 + 0) * 3 + dy) * 3 + dx] * a2[0]
                         + w[((och * 2 + 1) * 3 + dy) * 3 + dx] * a2[1];
                }
            }
            int h = och >> 1, comp = och & 1;
            outp[(((size_t)b * HEADS + h) * NPOS + p) * 2 + comp] = acc;
        }
        return;
    }
    int c = 2 * c2;
    int px0 = quarter * 7;
    float2 wgt[9];
#pragma unroll
    for (int k = 0; k < 9; k++)
        wgt[k] = make_float2(dww[c * 9 + k], dww[(c + 1) * 9 + k]);
    float2 bias = *(const float2*)&dwb[c];
    float2 gmm = *(const float2*)&gamma[c];
    float2 vr2 = *(const float2*)&var[c];
    float2 sc = make_float2(gmm.x * rsqrtf(vr2.x + 1e-5f), gmm.y * rsqrtf(vr2.y + 1e-5f));
    float2 bm = *(const float2*)&mean[c];
    float2 bb = *(const float2*)&beta[c];

    const float* basep = g_xpool + (size_t)b * NPOS * DIM + c;
    float2 vin[3][9];
#pragma unroll
    for (int r = 0; r < 3; r++) {
        int row = py - 1 + r;
        bool vr = (unsigned)row < PP;
#pragma unroll
        for (int cc = 0; cc < 9; cc++) {
            int col = px0 - 1 + cc;
            vin[r][cc] = (vr && (unsigned)col < PP)
                       ? *(const float2*)&basep[(size_t)(row * PP + col) * DIM]
                       : make_float2(0.f, 0.f);
        }
    }
    __half* outp = g_vmid_h + ((size_t)b * NPOS + py * PP + px0) * DIM + c;
#pragma unroll
    for (int i = 0; i < 7; i++) {
        float ax = bias.x, ay = bias.y;
#pragma unroll
        for (int r = 0; r < 3; r++)
#pragma unroll
            for (int d = 0; d < 3; d++) {
                ax = fmaf(wgt[r * 3 + d].x, vin[r][i + d].x, ax);
                ay = fmaf(wgt[r * 3 + d].y, vin[r][i + d].y, ay);
            }
        ax = (ax - bm.x) * sc.x + bb.x;
        ay = (ay - bm.y) * sc.y + bb.y;
        ax = 0.5f * ax * (1.f + erff(ax * 0.70710678118654752f));
        ay = 0.5f * ay * (1.f + erff(ay * 0.70710678118654752f));
        *(uint32_t*)&outp[(size_t)i * DIM] = pack_h2(ax, ay);
    }
}

// ---------------- fp16 mma GEMM: C[M,N] = A[M,K]*B[N,K]^T + bias -----------
__global__ __launch_bounds__(256) void gemm_h_kernel(
        const __half* __restrict__ A, const __half* __restrict__ B,
        const float* __restrict__ bias, void* __restrict__ Cv,
        int M, int N, int K, int out_half) {
    __shared__ uint2 As2[2][2][128][4];
    __shared__ uint2 Bs2[2][2][128][4];
    int tid = threadIdx.x;
    int lane = tid & 31, w = tid >> 5, g = lane >> 2, tig = lane & 3;
    int wm = w >> 1, wn = w & 1;
    int m0 = blockIdx.y * 128, n0 = blockIdx.x * 128;
    float c[2][8][4] = {};

    int nchunks = K >> 5;
    int arow[2], aq[2];
#pragma unroll
    for (int i = 0; i < 2; i++) { int s = tid + i * 256; arow[i] = s >> 2; aq[i] = s & 3; }
    uint4 ra[2], rb[2];

#pragma unroll
    for (int i = 0; i < 2; i++) {
        ra[i] = *(const uint4*)&A[(size_t)(m0 + arow[i]) * K + aq[i] * 8];
        rb[i] = *(const uint4*)&B[(size_t)(n0 + arow[i]) * K + aq[i] * 8];
    }

#pragma unroll
    for (int i = 0; i < 2; i++) {
        uint32_t* pa = (uint32_t*)&As2[0][aq[i] >> 1][arow[i]][0] + (aq[i] & 1);
        pa[0] = ra[i].x; pa[2] = ra[i].y; pa[4] = ra[i].z; pa[6] = ra[i].w;
        uint32_t* pb = (uint32_t*)&Bs2[0][aq[i] >> 1][arow[i]][0] + (aq[i] & 1);
        pb[0] = rb[i].x; pb[2] = rb[i].y; pb[4] = rb[i].z; pb[6] = rb[i].w;
    }
    __syncthreads();

    for (int kc = 0; kc < nchunks; kc++) {
        int cur = kc & 1;
        if (kc + 1 < nchunks) {
            int ko = (kc + 1) * 32;
#pragma unroll
            for (int i = 0; i < 2; i++) {
                ra[i] = *(const uint4*)&A[(size_t)(m0 + arow[i]) * K + ko + aq[i] * 8];
                rb[i] = *(const uint4*)&B[(size_t)(n0 + arow[i]) * K + ko + aq[i] * 8];
            }
        }
#pragma unroll
        for (int kg = 0; kg < 2; kg++) {
            uint2 a00 = As2[cur][kg][wm * 32 + g][tig];
            uint2 a08 = As2[cur][kg][wm * 32 + 8 + g][tig];
            uint2 a16 = As2[cur][kg][wm * 32 + 16 + g][tig];
            uint2 a24 = As2[cur][kg][wm * 32 + 24 + g][tig];
#pragma unroll
            for (int nt = 0; nt < 8; nt++) {
                uint2 bb = Bs2[cur][kg][wn * 64 + nt * 8 + g][tig];
                mma_h(c[0][nt], a00.x, a08.x, a00.y, a08.y, bb.x, bb.y);
                mma_h(c[1][nt], a16.x, a24.x, a16.y, a24.y, bb.x, bb.y);
            }
        }
        if (kc + 1 < nchunks) {
            int nxt = cur ^ 1;
#pragma unroll
            for (int i = 0; i < 2; i++) {
                uint32_t* pa = (uint32_t*)&As2[nxt][aq[i] >> 1][arow[i]][0] + (aq[i] & 1);
                pa[0] = ra[i].x; pa[2] = ra[i].y; pa[4] = ra[i].z; pa[6] = ra[i].w;
                uint32_t* pb = (uint32_t*)&Bs2[nxt][aq[i] >> 1][arow[i]][0] + (aq[i] & 1);
                pb[0] = rb[i].x; pb[2] = rb[i].y; pb[4] = rb[i].z; pb[6] = rb[i].w;
            }
            __syncthreads();
        }
    }
#pragma unroll
    for (int mt = 0; mt < 2; mt++) {
        int r = m0 + wm * 32 + mt * 16 + g;
#pragma unroll
        for (int nt = 0; nt < 8; nt++) {
            int n = n0 + wn * 64 + nt * 8 + 2 * tig;
            float bx = bias[n], by = bias[n + 1];
            float o0 = c[mt][nt][0] + bx, o1 = c[mt][nt][1] + by;
            float o2 = c[mt][nt][2] + bx, o3 = c[mt][nt][3] + by;
            if (out_half) {
                __half* C = (__half*)Cv;
                *(uint32_t*)&C[(size_t)r * N + n] = pack_h2(o0, o1);
                *(uint32_t*)&C[(size_t)(r + 8) * N + n] = pack_h2(o2, o3);
            } else {
                float* C = (float*)Cv;
                *(float2*)&C[(size_t)r * N + n] = make_float2(o0, o1);
                *(float2*)&C[(size_t)(r + 8) * N + n] = make_float2(o2, o3);
            }
        }
    }
}

// ---------------- 5) attention: 2 q-tiles per sweep share ldmatrix V -------
// 13 warps (416 thr). Per jg: 4 ldmatrix + 2 kxy LDS serve BOTH q-tiles
// (halves L1 traffic vs R16). ONES-mma row sums per tile (R14-validated).
#define VROW 72
#define VTILE (16 * VROW)            // halves per jg tile (1152)
#define KXY_OFF (49 * VTILE * 2)     // 112896 bytes
#define ATTN_SMEM_SZ (KXY_OFF + NPOS * 8)   // +6272 = 119168
#define ATH 416

__global__ __launch_bounds__(ATH, 1) void attn_h_kernel() {
    extern __shared__ char smc[];
    __half* vtile = (__half*)smc;
    float2* kxy = (float2*)(smc + KXY_OFF);
    int h = blockIdx.x, b = blockIdx.y;
    int tid = threadIdx.x, lane = tid & 31, w = tid >> 5;
    int g = lane >> 2, tig = lane & 3;
    const uint32_t ONES = 0x3C003C00u;

    const __half* vsrc = g_v_h + (size_t)b * NPOS * INNER + h * DH;
    for (int i = tid; i < NPOS * 16; i += ATH) {
        int j = i >> 4, q = i & 15;
        uint2 v = *(const uint2*)&vsrc[(size_t)j * INNER + q * 4];
        *(uint2*)&vtile[(j >> 4) * VTILE + (j & 15) * VROW + q * 4] = v;
    }
    const float* ksrc = g_k + ((size_t)b * HEADS + h) * NPOS * 2;
    const float KSC = 0.125f * 1.4426950408889634f;
    for (int i = tid; i < NPOS; i += ATH) {
        float2 kv = ((const float2*)ksrc)[i];
        kxy[i] = make_float2(kv.x * KSC, kv.y * KSC);
    }
    __syncthreads();

    int mrow = (lane & 7) + ((lane >> 3) & 1) * 8;
    int nsub = (lane >> 4) * 8;
    uint32_t vbase = smem_u32(vtile) + (uint32_t)(mrow * VROW + nsub) * 2;

    const float2* qsrc = (const float2*)(g_q + ((size_t)b * HEADS + h) * NPOS * 2);
    __half* odst = g_ao_h + (size_t)b * NPOS * INNER + h * DH;

    for (int s = w; s < 25; s += 13) {
        int t0 = 2 * s, t1 = 2 * s + 1;       // t1==49 invalid at s==24
        bool v1 = t1 < 49;
        int r00 = t0 * 16 + g, r01 = r00 + 8;
        int r10 = t1 * 16 + g, r11 = r10 + 8;
        float2 qA0 = qsrc[r00], qA1 = qsrc[r01];
        float2 qB0 = v1 ? qsrc[r10] : make_float2(0.f, 0.f);
        float2 qB1 = v1 ? qsrc[r11] : make_float2(0.f, 0.f);
        float cA[8][4] = {}, cB[8][4] = {};
        float clA[4] = {}, clB[4] = {};
        for (int jg = 0; jg < 49; jg++) {
            float4 kk0 = *(const float4*)&kxy[jg * 16 + 2 * tig];
            float4 kk1 = *(const float4*)&kxy[jg * 16 + 2 * tig + 8];
            uint32_t a0 = exp2_h2(fmaf(qA0.x, kk0.x, qA0.y * kk0.y),
                                  fmaf(qA0.x, kk0.z, qA0.y * kk0.w));
            uint32_t a1 = exp2_h2(fmaf(qA1.x, kk0.x, qA1.y * kk0.y),
                                  fmaf(qA1.x, kk0.z, qA1.y * kk0.w));
            uint32_t a2 = exp2_h2(fmaf(qA0.x, kk1.x, qA0.y * kk1.y),
                                  fmaf(qA0.x, kk1.z, qA0.y * kk1.w));
            uint32_t a3 = exp2_h2(fmaf(qA1.x, kk1.x, qA1.y * kk1.y),
                                  fmaf(qA1.x, kk1.z, qA1.y * kk1.w));
            uint32_t a4 = exp2_h2(fmaf(qB0.x, kk0.x, qB0.y * kk0.y),
                                  fmaf(qB0.x, kk0.z, qB0.y * kk0.w));
            uint32_t a5 = exp2_h2(fmaf(qB1.x, kk0.x, qB1.y * kk0.y),
                                  fmaf(qB1.x, kk0.z, qB1.y * kk0.w));
            uint32_t a6 = exp2_h2(fmaf(qB0.x, kk1.x, qB0.y * kk1.y),
                                  fmaf(qB0.x, kk1.z, qB0.y * kk1.w));
            uint32_t a7 = exp2_h2(fmaf(qB1.x, kk1.x, qB1.y * kk1.y),
                                  fmaf(qB1.x, kk1.z, qB1.y * kk1.w));
            uint32_t vb = vbase + (uint32_t)jg * (VTILE * 2);
#pragma unroll
            for (int p = 0; p < 4; p++) {
                uint32_t r0r, r1r, r2r, r3r;
                asm volatile(
                    "ldmatrix.sync.aligned.m8n8.x4.trans.shared.b16 "
                    "{%0,%1,%2,%3}, [%4];"
                    : "=r"(r0r), "=r"(r1r), "=r"(r2r), "=r"(r3r)
                    : "r"(vb + (uint32_t)(p * 32)));
                mma_h(cA[2 * p], a0, a1, a2, a3, r0r, r1r);
                mma_h(cA[2 * p + 1], a0, a1, a2, a3, r2r, r3r);
                mma_h(cB[2 * p], a4, a5, a6, a7, r0r, r1r);
                mma_h(cB[2 * p + 1], a4, a5, a6, a7, r2r, r3r);
            }
            mma_h(clA, a0, a1, a2, a3, ONES, ONES);
            mma_h(clB, a4, a5, a6, a7, ONES, ONES);
        }
        float i00 = 1.f / clA[0], i01 = 1.f / clA[2];
#pragma unroll
        for (int nt = 0; nt < 8; nt++) {
            int n = nt * 8 + 2 * tig;
            *(uint32_t*)&odst[(size_t)r00 * INNER + n] = pack_h2(cA[nt][0] * i00, cA[nt][1] * i00);
            *(uint32_t*)&odst[(size_t)r01 * INNER + n] = pack_h2(cA[nt][2] * i01, cA[nt][3] * i01);
        }
        if (v1) {
            float i10 = 1.f / clB[0], i11 = 1.f / clB[2];
#pragma unroll
            for (int nt = 0; nt < 8; nt++) {
                int n = nt * 8 + 2 * tig;
                *(uint32_t*)&odst[(size_t)r10 * INNER + n] = pack_h2(cB[nt][0] * i10, cB[nt][1] * i10);
                *(uint32_t*)&odst[(size_t)r11 * INNER + n] = pack_h2(cB[nt][2] * i11, cB[nt][3] * i11);
            }
        }
    }
}

// ---------------- 7) bicubic x2 upsample (reads fp16 y28) ------------------
__global__ void upsample3_kernel(float* __restrict__ out) {
    extern __shared__ float tmp[];   // [2][PP][DIM] dynamic (57344 B)
    float* tmp0 = tmp;
    float* tmp1 = tmp + PP * DIM;
    int m = blockIdx.x, b = blockIdx.y, c = threadIdx.x;
    int ry[5];
#pragma unroll
    for (int r = 0; r < 5; r++) ry[r] = min(max(m - 2 + r, 0), PP - 1);
    const __half* basep = g_y28_h + (size_t)b * NPOS * DIM + c;
#pragma unroll 7
    for (int ix = 0; ix < PP; ix++) {
        float v0 = __half2float(basep[(size_t)(ry[0] * PP + ix) * DIM]);
        float v1 = __half2float(basep[(size_t)(ry[1] * PP + ix) * DIM]);
        float v2 = __half2float(basep[(size_t)(ry[2] * PP + ix) * DIM]);
        float v3 = __half2float(basep[(size_t)(ry[3] * PP + ix) * DIM]);
        float v4 = __half2float(basep[(size_t)(ry[4] * PP + ix) * DIM]);
        tmp0[ix * DIM + c] = c_W75[0] * v0 + c_W75[1] * v1 + c_W75[2] * v2 + c_W75[3] * v3;
        tmp1[ix * DIM + c] = c_W25[0] * v1 + c_W25[1] * v2 + c_W25[2] * v3 + c_W25[3] * v4;
    }
    __syncthreads();
    float* orow0 = out + ((size_t)b * IMG * IMG + (2 * m) * IMG) * DIM + c;
    float* orow1 = orow0 + (size_t)IMG * DIM;
#pragma unroll 4
    for (int ox = 0; ox < IMG; ox++) {
        int ix0; const float* wx;
        if (ox & 1) { ix0 = (ox - 1) >> 1; wx = c_W25; }
        else        { ix0 = (ox >> 1) - 1; wx = c_W75; }
        int sx0 = min(max(ix0 - 1, 0), PP - 1);
        int sx1 = min(max(ix0 + 0, 0), PP - 1);
        int sx2 = min(max(ix0 + 1, 0), PP - 1);
        int sx3 = min(max(ix0 + 2, 0), PP - 1);
        float a0 = wx[0] * tmp0[sx0 * DIM + c] + wx[1] * tmp0[sx1 * DIM + c]
                 + wx[2] * tmp0[sx2 * DIM + c] + wx[3] * tmp0[sx3 * DIM + c];
        float a1 = wx[0] * tmp1[sx0 * DIM + c] + wx[1] * tmp1[sx1 * DIM + c]
                 + wx[2] * tmp1[sx2 * DIM + c] + wx[3] * tmp1[sx3 * DIM + c];
        orow0[(size_t)ox * DIM] = a0;
        orow1[(size_t)ox * DIM] = a1;
    }
}

// ---------------- launch ---------------------------------------------------
extern "C" void kernel_launch(void* const* d_in, const int* in_sizes, int n_in,
                              void* d_out, int out_size) {
    const float* x     = (const float*)d_in[0];
    const float* q_w   = (const float*)d_in[1];
    const float* q_b   = (const float*)d_in[2];
    const float* k_w   = (const float*)d_in[3];
    const float* k_b   = (const float*)d_in[4];
    const float* dw_w  = (const float*)d_in[5];
    const float* dw_b  = (const float*)d_in[6];
    const float* bn_g  = (const float*)d_in[7];
    const float* bn_b  = (const float*)d_in[8];
    const float* bn_m  = (const float*)d_in[9];
    const float* bn_v  = (const float*)d_in[10];
    const float* pw_w  = (const float*)d_in[11];
    const float* pw_b  = (const float*)d_in[12];
    const float* out_w = (const float*)d_in[13];
    const float* out_b = (const float*)d_in[14];
    float* out = (float*)d_out;

    const int UPS_SMEM = 2 * PP * DIM * (int)sizeof(float);   // 57344
    cudaFuncSetAttribute(attn_h_kernel, cudaFuncAttributeMaxDynamicSharedMemorySize, ATTN_SMEM_SZ);
    cudaFuncSetAttribute(upsample3_kernel, cudaFuncAttributeMaxDynamicSharedMemorySize, UPS_SMEM);

    void *p_vmid, *p_v, *p_ao, *p_y28, *p_pww, *p_oww;
    cudaGetSymbolAddress(&p_vmid, g_vmid_h);
    cudaGetSymbolAddress(&p_v, g_v_h);
    cudaGetSymbolAddress(&p_ao, g_ao_h);
    cudaGetSymbolAddress(&p_y28, g_y28_h);
    cudaGetSymbolAddress(&p_pww, g_pww_h);
    cudaGetSymbolAddress(&p_oww, g_oww_h);

    pool_part_kernel<<<dim3(5, PP, BATCH), 128>>>(x, pw_w, out_w);
    dw_part_kernel<<<dim3(5, PP, BATCH), 128>>>(dw_w, dw_b, bn_g, bn_b, bn_m, bn_v,
                                                q_w, q_b, k_w, k_b);
    gemm_h_kernel<<<dim3(INNER / 128, (BATCH * NPOS) / 128), 256>>>(
        (const __half*)p_vmid, (const __half*)p_pww, pw_b, p_v,
        BATCH * NPOS, INNER, DIM, 1);
    attn_h_kernel<<<dim3(HEADS, BATCH), ATH, ATTN_SMEM_SZ>>>();
    gemm_h_kernel<<<dim3(DIM / 128, (BATCH * NPOS) / 128), 256>>>(
        (const __half*)p_ao, (const __half*)p_oww, out_b, p_y28,
        BATCH * NPOS, DIM, INNER, 1);
    upsample3_kernel<<<dim3(PP, BATCH), 256, UPS_SMEM>>>(out);
}